// round 3
// baseline (speedup 1.0000x reference)
#include <cuda_runtime.h>
#include <math.h>

#define BB  2
#define EE  1024
#define TT  2048
#define HH  16
#define DHD 64
#define NTOK (BB*TT)

// ---- scratch (device globals: allocation-free rule) ----
__device__ float g_qp[(size_t)BB*EE*TT];            // 16 MB
__device__ float g_kp[(size_t)BB*EE*TT];
__device__ float g_vp[(size_t)BB*EE*TT];
__device__ float g_ao[(size_t)BB*EE*TT];
__device__ float g_sc[(size_t)BB*HH*TT*TT];         // 512 MB scores/attn

// ============================================================================
// conv1x1: C[b,o,t] = mask[b,t] * sum_c W[o,c]*X[b,c,t] + bias[o]
// 128x128 tile, BK=16, 256 threads, 8x8 microtile.
// ============================================================================
__global__ __launch_bounds__(256) void conv1x1_k(
    const float* __restrict__ W, const float* __restrict__ X,
    const float* __restrict__ bias, const float* __restrict__ mask,
    float* __restrict__ C)
{
    __shared__ float As[16][128];   // [k][m]  (W transposed)
    __shared__ float Bs[16][128];   // [k][n]

    const int jBase = blockIdx.x * 128;          // global token block (b*T + t)
    const int rowBase = blockIdx.y * 128;        // output channel block
    const int b = jBase / TT;
    const int t0 = jBase - b * TT;               // 128 | 2048 -> never straddles batches
    const float* Xb = X + (size_t)b * EE * TT;
    const int tid = threadIdx.x;
    const int ty = tid >> 4;
    const int tx = tid & 15;

    float acc[8][8];
#pragma unroll
    for (int i = 0; i < 8; i++)
#pragma unroll
        for (int j = 0; j < 8; j++) acc[i][j] = 0.f;

    for (int k0 = 0; k0 < EE; k0 += 16) {
#pragma unroll
        for (int i = 0; i < 2; i++) {            // W tile: 128x16, store transposed
            int e = (tid + i * 256) * 4;
            int m = e >> 4, kk = e & 15;
            float4 w4 = *(const float4*)(W + (size_t)(rowBase + m) * EE + k0 + kk);
            As[kk + 0][m] = w4.x; As[kk + 1][m] = w4.y;
            As[kk + 2][m] = w4.z; As[kk + 3][m] = w4.w;
        }
#pragma unroll
        for (int i = 0; i < 2; i++) {            // X tile: 16x128, natural
            int e = (tid + i * 256) * 4;
            int c = e >> 7, jj = e & 127;
            *(float4*)&Bs[c][jj] =
                *(const float4*)(Xb + (size_t)(k0 + c) * TT + t0 + jj);
        }
        __syncthreads();
#pragma unroll
        for (int kk = 0; kk < 16; kk++) {
            float a[8], bb[8];
            *(float4*)&a[0]  = *(const float4*)&As[kk][ty * 8];
            *(float4*)&a[4]  = *(const float4*)&As[kk][ty * 8 + 4];
            *(float4*)&bb[0] = *(const float4*)&Bs[kk][tx * 8];
            *(float4*)&bb[4] = *(const float4*)&Bs[kk][tx * 8 + 4];
#pragma unroll
            for (int i = 0; i < 8; i++)
#pragma unroll
                for (int j = 0; j < 8; j++)
                    acc[i][j] = fmaf(a[i], bb[j], acc[i][j]);
        }
        __syncthreads();
    }

    float mv[8];
#pragma unroll
    for (int j = 0; j < 8; j++) mv[j] = mask[b * TT + t0 + tx * 8 + j];
    float* Cb = C + (size_t)b * EE * TT;
#pragma unroll
    for (int i = 0; i < 8; i++) {
        int row = rowBase + ty * 8 + i;
        float bi = bias[row];
        float4 o0, o1;
        o0.x = fmaf(acc[i][0], mv[0], bi); o0.y = fmaf(acc[i][1], mv[1], bi);
        o0.z = fmaf(acc[i][2], mv[2], bi); o0.w = fmaf(acc[i][3], mv[3], bi);
        o1.x = fmaf(acc[i][4], mv[4], bi); o1.y = fmaf(acc[i][5], mv[5], bi);
        o1.z = fmaf(acc[i][6], mv[6], bi); o1.w = fmaf(acc[i][7], mv[7], bi);
        float* p = Cb + (size_t)row * TT + t0 + tx * 8;
        *(float4*)p = o0;
        *(float4*)(p + 4) = o1;
    }
}

// ============================================================================
// scores: S[bh,q,k] = (sum_d qh[d,q]*kh[d,k]) * qmask[q]*kmask[k] / 32
// per (b,h): [T,T] output, K=DH=64.  128x128 tile, BK=16.
// ============================================================================
__global__ __launch_bounds__(256) void scores_k(
    const float* __restrict__ qmask, const float* __restrict__ kmask)
{
    __shared__ float As[16][128];   // [d][q]
    __shared__ float Bs[16][128];   // [d][k]
    const int bh = blockIdx.z;
    const int b = bh >> 4;
    const int h = bh & 15;
    const int kBase = blockIdx.x * 128;
    const int qBase = blockIdx.y * 128;
    const float* qb = g_qp + (size_t)b * EE * TT + (size_t)h * DHD * TT;
    const float* kb = g_kp + (size_t)b * EE * TT + (size_t)h * DHD * TT;
    const int tid = threadIdx.x, ty = tid >> 4, tx = tid & 15;

    float acc[8][8];
#pragma unroll
    for (int i = 0; i < 8; i++)
#pragma unroll
        for (int j = 0; j < 8; j++) acc[i][j] = 0.f;

    for (int d0 = 0; d0 < DHD; d0 += 16) {
#pragma unroll
        for (int i = 0; i < 2; i++) {
            int e = (tid + i * 256) * 4;
            int d = e >> 7, qq = e & 127;
            *(float4*)&As[d][qq] =
                *(const float4*)(qb + (size_t)(d0 + d) * TT + qBase + qq);
        }
#pragma unroll
        for (int i = 0; i < 2; i++) {
            int e = (tid + i * 256) * 4;
            int d = e >> 7, kk = e & 127;
            *(float4*)&Bs[d][kk] =
                *(const float4*)(kb + (size_t)(d0 + d) * TT + kBase + kk);
        }
        __syncthreads();
#pragma unroll
        for (int dd = 0; dd < 16; dd++) {
            float a[8], bb[8];
            *(float4*)&a[0]  = *(const float4*)&As[dd][ty * 8];
            *(float4*)&a[4]  = *(const float4*)&As[dd][ty * 8 + 4];
            *(float4*)&bb[0] = *(const float4*)&Bs[dd][tx * 8];
            *(float4*)&bb[4] = *(const float4*)&Bs[dd][tx * 8 + 4];
#pragma unroll
            for (int i = 0; i < 8; i++)
#pragma unroll
                for (int j = 0; j < 8; j++)
                    acc[i][j] = fmaf(a[i], bb[j], acc[i][j]);
        }
        __syncthreads();
    }

    float qmv[8], kmv[8];
#pragma unroll
    for (int i = 0; i < 8; i++) qmv[i] = qmask[b * TT + qBase + ty * 8 + i];
#pragma unroll
    for (int j = 0; j < 8; j++)
        kmv[j] = kmask[b * TT + kBase + tx * 8 + j] * 0.03125f;  // 1/sqrt(1024)

    float* Sb = g_sc + (size_t)bh * TT * TT;
#pragma unroll
    for (int i = 0; i < 8; i++) {
        int qrow = qBase + ty * 8 + i;
        float s = qmv[i];
        float4 o0, o1;
        o0.x = acc[i][0] * s * kmv[0]; o0.y = acc[i][1] * s * kmv[1];
        o0.z = acc[i][2] * s * kmv[2]; o0.w = acc[i][3] * s * kmv[3];
        o1.x = acc[i][4] * s * kmv[4]; o1.y = acc[i][5] * s * kmv[5];
        o1.z = acc[i][6] * s * kmv[6]; o1.w = acc[i][7] * s * kmv[7];
        float* p = Sb + (size_t)qrow * TT + kBase + tx * 8;
        *(float4*)p = o0;
        *(float4*)(p + 4) = o1;
    }
}

// ============================================================================
// row softmax (axis = k) in place, then * kmask[k].
// One block per (bh, q) row; 256 threads x 8 elems.
// ============================================================================
__global__ __launch_bounds__(256) void softmax_k(const float* __restrict__ kmask)
{
    const size_t row = blockIdx.x;                 // (b*H + h)*T + q
    const int b = (int)(row / ((size_t)HH * TT));
    float* S = g_sc + row * TT;
    const float* km = kmask + (size_t)b * TT;
    const int tid = threadIdx.x;

    float4 v0 = *(const float4*)&S[tid * 4];
    float4 v1 = *(const float4*)&S[1024 + tid * 4];

    float lm = fmaxf(fmaxf(fmaxf(v0.x, v0.y), fmaxf(v0.z, v0.w)),
                     fmaxf(fmaxf(v1.x, v1.y), fmaxf(v1.z, v1.w)));
    __shared__ float red[256];
    red[tid] = lm; __syncthreads();
#pragma unroll
    for (int s = 128; s > 0; s >>= 1) {
        if (tid < s) red[tid] = fmaxf(red[tid], red[tid + s]);
        __syncthreads();
    }
    float m = red[0];
    __syncthreads();

    float e[8];
    e[0] = expf(v0.x - m); e[1] = expf(v0.y - m);
    e[2] = expf(v0.z - m); e[3] = expf(v0.w - m);
    e[4] = expf(v1.x - m); e[5] = expf(v1.y - m);
    e[6] = expf(v1.z - m); e[7] = expf(v1.w - m);

    float ls = (e[0] + e[1]) + (e[2] + e[3]) + (e[4] + e[5]) + (e[6] + e[7]);
    red[tid] = ls; __syncthreads();
#pragma unroll
    for (int s = 128; s > 0; s >>= 1) {
        if (tid < s) red[tid] += red[tid + s];
        __syncthreads();
    }
    float inv = 1.0f / red[0];

    float4 o0, o1;
    o0.x = e[0] * inv * km[tid * 4 + 0];
    o0.y = e[1] * inv * km[tid * 4 + 1];
    o0.z = e[2] * inv * km[tid * 4 + 2];
    o0.w = e[3] * inv * km[tid * 4 + 3];
    o1.x = e[4] * inv * km[1024 + tid * 4 + 0];
    o1.y = e[5] * inv * km[1024 + tid * 4 + 1];
    o1.z = e[6] * inv * km[1024 + tid * 4 + 2];
    o1.w = e[7] * inv * km[1024 + tid * 4 + 3];
    *(float4*)&S[tid * 4] = o0;
    *(float4*)&S[1024 + tid * 4] = o1;
}

// ============================================================================
// O[bh,d,k] = sum_q vh[d,q] * attn[q,k].   M=64, N=T, K=T per (b,h).
// 64x128 tile, BK=32, 256 threads, 4x8 microtile.
// ============================================================================
__global__ __launch_bounds__(256) void av_k()
{
    __shared__ float As[32][68];    // [q][d] (+pad, 16B-aligned rows)
    __shared__ float Bs[32][128];   // [q][k]
    const int bh = blockIdx.z;
    const int b = bh >> 4, h = bh & 15;
    const int kBase = blockIdx.x * 128;
    const float* vb = g_vp + (size_t)b * EE * TT + (size_t)h * DHD * TT;
    const float* Sb = g_sc + (size_t)bh * TT * TT;
    const int tid = threadIdx.x, ty = tid >> 4, tx = tid & 15;

    float acc[4][8];
#pragma unroll
    for (int i = 0; i < 4; i++)
#pragma unroll
        for (int j = 0; j < 8; j++) acc[i][j] = 0.f;

    for (int q0 = 0; q0 < TT; q0 += 32) {
#pragma unroll
        for (int i = 0; i < 2; i++) {            // V tile 64x32, store transposed
            int e = (tid + i * 256) * 4;
            int d = e >> 5, qq = e & 31;
            float4 v4 = *(const float4*)(vb + (size_t)d * TT + q0 + qq);
            As[qq + 0][d] = v4.x; As[qq + 1][d] = v4.y;
            As[qq + 2][d] = v4.z; As[qq + 3][d] = v4.w;
        }
#pragma unroll
        for (int i = 0; i < 4; i++) {            // attn tile 32x128, natural
            int e = (tid + i * 256) * 4;
            int qq = e >> 7, kk = e & 127;
            *(float4*)&Bs[qq][kk] =
                *(const float4*)(Sb + (size_t)(q0 + qq) * TT + kBase + kk);
        }
        __syncthreads();
#pragma unroll
        for (int qq = 0; qq < 32; qq++) {
            float a[4], bb[8];
            *(float4*)&a[0]  = *(const float4*)&As[qq][ty * 4];
            *(float4*)&bb[0] = *(const float4*)&Bs[qq][tx * 8];
            *(float4*)&bb[4] = *(const float4*)&Bs[qq][tx * 8 + 4];
#pragma unroll
            for (int i = 0; i < 4; i++)
#pragma unroll
                for (int j = 0; j < 8; j++)
                    acc[i][j] = fmaf(a[i], bb[j], acc[i][j]);
        }
        __syncthreads();
    }

    float* ob = g_ao + (size_t)b * EE * TT + (size_t)h * DHD * TT;
#pragma unroll
    for (int i = 0; i < 4; i++) {
        int d = ty * 4 + i;
        float4 o0, o1;
        o0.x = acc[i][0]; o0.y = acc[i][1]; o0.z = acc[i][2]; o0.w = acc[i][3];
        o1.x = acc[i][4]; o1.y = acc[i][5]; o1.z = acc[i][6]; o1.w = acc[i][7];
        float* p = ob + (size_t)d * TT + kBase + tx * 8;
        *(float4*)p = o0;
        *(float4*)(p + 4) = o1;
    }
}

// ============================================================================
// launch
// ============================================================================
extern "C" void kernel_launch(void* const* d_in, const int* in_sizes, int n_in,
                              void* d_out, int out_size)
{
    const float* q  = (const float*)d_in[0];
    const float* k  = (const float*)d_in[1];
    const float* v  = (const float*)d_in[2];
    const float* qm = (const float*)d_in[3];
    const float* km = (const float*)d_in[4];
    const float* vm = (const float*)d_in[5];
    const float* Wq = (const float*)d_in[6];
    const float* bq = (const float*)d_in[7];
    const float* Wk = (const float*)d_in[8];
    const float* bk = (const float*)d_in[9];
    const float* Wv = (const float*)d_in[10];
    const float* bv = (const float*)d_in[11];
    const float* Wo = (const float*)d_in[12];
    const float* bo = (const float*)d_in[13];
    float* out = (float*)d_out;

    float *p_qp, *p_kp, *p_vp, *p_ao;
    cudaGetSymbolAddress((void**)&p_qp, g_qp);
    cudaGetSymbolAddress((void**)&p_kp, g_kp);
    cudaGetSymbolAddress((void**)&p_vp, g_vp);
    cudaGetSymbolAddress((void**)&p_ao, g_ao);

    dim3 cgrid(NTOK / 128, EE / 128);
    conv1x1_k<<<cgrid, 256>>>(Wq, q, bq, qm, p_qp);
    conv1x1_k<<<cgrid, 256>>>(Wk, k, bk, km, p_kp);
    conv1x1_k<<<cgrid, 256>>>(Wv, v, bv, vm, p_vp);

    dim3 sgrid(TT / 128, TT / 128, BB * HH);
    scores_k<<<sgrid, 256>>>(qm, km);

    softmax_k<<<BB * HH * TT, 256>>>(km);

    dim3 agrid(TT / 128, 1, BB * HH);
    av_k<<<agrid, 256>>>();

    conv1x1_k<<<cgrid, 256>>>(Wo, p_ao, bo, km, out);
}

// round 6
// speedup vs baseline: 1.0000x; 1.0000x over previous
#include <cuda_runtime.h>
#include <math.h>

#define BB  2
#define EE  1024
#define TT  2048
#define HH  16
#define DHD 64
#define NTOK (BB*TT)

// ---- scratch (device globals: allocation-free rule) ----
__device__ float g_qp[(size_t)BB*EE*TT];            // 16 MB
__device__ float g_kp[(size_t)BB*EE*TT];
__device__ float g_vp[(size_t)BB*EE*TT];
__device__ float g_ao[(size_t)BB*EE*TT];
__device__ float g_sc[(size_t)BB*HH*TT*TT];         // 512 MB scores/attn

// ============================================================================
// conv1x1: C[b,o,t] = mask[b,t] * sum_c W[o,c]*X[b,c,t] + bias[o]
// 128x128 tile, BK=16, 256 threads, 8x8 microtile.
// ============================================================================
__global__ __launch_bounds__(256) void conv1x1_k(
    const float* __restrict__ W, const float* __restrict__ X,
    const float* __restrict__ bias, const float* __restrict__ mask,
    float* __restrict__ C)
{
    __shared__ float As[16][128];   // [k][m]  (W transposed)
    __shared__ float Bs[16][128];   // [k][n]

    const int jBase = blockIdx.x * 128;          // global token block (b*T + t)
    const int rowBase = blockIdx.y * 128;        // output channel block
    const int b = jBase / TT;
    const int t0 = jBase - b * TT;               // 128 | 2048 -> never straddles batches
    const float* Xb = X + (size_t)b * EE * TT;
    const int tid = threadIdx.x;
    const int ty = tid >> 4;
    const int tx = tid & 15;

    float acc[8][8];
#pragma unroll
    for (int i = 0; i < 8; i++)
#pragma unroll
        for (int j = 0; j < 8; j++) acc[i][j] = 0.f;

    for (int k0 = 0; k0 < EE; k0 += 16) {
#pragma unroll
        for (int i = 0; i < 2; i++) {            // W tile: 128x16, store transposed
            int e = (tid + i * 256) * 4;
            int m = e >> 4, kk = e & 15;
            float4 w4 = *(const float4*)(W + (size_t)(rowBase + m) * EE + k0 + kk);
            As[kk + 0][m] = w4.x; As[kk + 1][m] = w4.y;
            As[kk + 2][m] = w4.z; As[kk + 3][m] = w4.w;
        }
#pragma unroll
        for (int i = 0; i < 2; i++) {            // X tile: 16x128, natural
            int e = (tid + i * 256) * 4;
            int c = e >> 7, jj = e & 127;
            *(float4*)&Bs[c][jj] =
                *(const float4*)(Xb + (size_t)(k0 + c) * TT + t0 + jj);
        }
        __syncthreads();
#pragma unroll
        for (int kk = 0; kk < 16; kk++) {
            float a[8], bb[8];
            *(float4*)&a[0]  = *(const float4*)&As[kk][ty * 8];
            *(float4*)&a[4]  = *(const float4*)&As[kk][ty * 8 + 4];
            *(float4*)&bb[0] = *(const float4*)&Bs[kk][tx * 8];
            *(float4*)&bb[4] = *(const float4*)&Bs[kk][tx * 8 + 4];
#pragma unroll
            for (int i = 0; i < 8; i++)
#pragma unroll
                for (int j = 0; j < 8; j++)
                    acc[i][j] = fmaf(a[i], bb[j], acc[i][j]);
        }
        __syncthreads();
    }

    float mv[8];
#pragma unroll
    for (int j = 0; j < 8; j++) mv[j] = mask[b * TT + t0 + tx * 8 + j];
    float* Cb = C + (size_t)b * EE * TT;
#pragma unroll
    for (int i = 0; i < 8; i++) {
        int row = rowBase + ty * 8 + i;
        float bi = bias[row];
        float4 o0, o1;
        o0.x = fmaf(acc[i][0], mv[0], bi); o0.y = fmaf(acc[i][1], mv[1], bi);
        o0.z = fmaf(acc[i][2], mv[2], bi); o0.w = fmaf(acc[i][3], mv[3], bi);
        o1.x = fmaf(acc[i][4], mv[4], bi); o1.y = fmaf(acc[i][5], mv[5], bi);
        o1.z = fmaf(acc[i][6], mv[6], bi); o1.w = fmaf(acc[i][7], mv[7], bi);
        float* p = Cb + (size_t)row * TT + t0 + tx * 8;
        *(float4*)p = o0;
        *(float4*)(p + 4) = o1;
    }
}

// ============================================================================
// scores: S[bh,q,k] = (sum_d qh[d,q]*kh[d,k]) * qmask[q]*kmask[k] / 32
// per (b,h): [T,T] output, K=DH=64.  128x128 tile, BK=16.
// ============================================================================
__global__ __launch_bounds__(256) void scores_k(
    const float* __restrict__ qmask, const float* __restrict__ kmask)
{
    __shared__ float As[16][128];   // [d][q]
    __shared__ float Bs[16][128];   // [d][k]
    const int bh = blockIdx.z;
    const int b = bh >> 4;
    const int h = bh & 15;
    const int kBase = blockIdx.x * 128;
    const int qBase = blockIdx.y * 128;
    const float* qb = g_qp + (size_t)b * EE * TT + (size_t)h * DHD * TT;
    const float* kb = g_kp + (size_t)b * EE * TT + (size_t)h * DHD * TT;
    const int tid = threadIdx.x, ty = tid >> 4, tx = tid & 15;

    float acc[8][8];
#pragma unroll
    for (int i = 0; i < 8; i++)
#pragma unroll
        for (int j = 0; j < 8; j++) acc[i][j] = 0.f;

    for (int d0 = 0; d0 < DHD; d0 += 16) {
#pragma unroll
        for (int i = 0; i < 2; i++) {
            int e = (tid + i * 256) * 4;
            int d = e >> 7, qq = e & 127;
            *(float4*)&As[d][qq] =
                *(const float4*)(qb + (size_t)(d0 + d) * TT + qBase + qq);
        }
#pragma unroll
        for (int i = 0; i < 2; i++) {
            int e = (tid + i * 256) * 4;
            int d = e >> 7, kk = e & 127;
            *(float4*)&Bs[d][kk] =
                *(const float4*)(kb + (size_t)(d0 + d) * TT + kBase + kk);
        }
        __syncthreads();
#pragma unroll
        for (int dd = 0; dd < 16; dd++) {
            float a[8], bb[8];
            *(float4*)&a[0]  = *(const float4*)&As[dd][ty * 8];
            *(float4*)&a[4]  = *(const float4*)&As[dd][ty * 8 + 4];
            *(float4*)&bb[0] = *(const float4*)&Bs[dd][tx * 8];
            *(float4*)&bb[4] = *(const float4*)&Bs[dd][tx * 8 + 4];
#pragma unroll
            for (int i = 0; i < 8; i++)
#pragma unroll
                for (int j = 0; j < 8; j++)
                    acc[i][j] = fmaf(a[i], bb[j], acc[i][j]);
        }
        __syncthreads();
    }

    float qmv[8], kmv[8];
#pragma unroll
    for (int i = 0; i < 8; i++) qmv[i] = qmask[b * TT + qBase + ty * 8 + i];
#pragma unroll
    for (int j = 0; j < 8; j++)
        kmv[j] = kmask[b * TT + kBase + tx * 8 + j] * 0.03125f;  // 1/sqrt(1024)

    float* Sb = g_sc + (size_t)bh * TT * TT;
#pragma unroll
    for (int i = 0; i < 8; i++) {
        int qrow = qBase + ty * 8 + i;
        float s = qmv[i];
        float4 o0, o1;
        o0.x = acc[i][0] * s * kmv[0]; o0.y = acc[i][1] * s * kmv[1];
        o0.z = acc[i][2] * s * kmv[2]; o0.w = acc[i][3] * s * kmv[3];
        o1.x = acc[i][4] * s * kmv[4]; o1.y = acc[i][5] * s * kmv[5];
        o1.z = acc[i][6] * s * kmv[6]; o1.w = acc[i][7] * s * kmv[7];
        float* p = Sb + (size_t)qrow * TT + kBase + tx * 8;
        *(float4*)p = o0;
        *(float4*)(p + 4) = o1;
    }
}

// ============================================================================
// row softmax (axis = k) in place, then * kmask[k].
// One block per (bh, q) row; 256 threads x 8 elems.
// ============================================================================
__global__ __launch_bounds__(256) void softmax_k(const float* __restrict__ kmask)
{
    const size_t row = blockIdx.x;                 // (b*H + h)*T + q
    const int b = (int)(row / ((size_t)HH * TT));
    float* S = g_sc + row * TT;
    const float* km = kmask + (size_t)b * TT;
    const int tid = threadIdx.x;

    float4 v0 = *(const float4*)&S[tid * 4];
    float4 v1 = *(const float4*)&S[1024 + tid * 4];

    float lm = fmaxf(fmaxf(fmaxf(v0.x, v0.y), fmaxf(v0.z, v0.w)),
                     fmaxf(fmaxf(v1.x, v1.y), fmaxf(v1.z, v1.w)));
    __shared__ float red[256];
    red[tid] = lm; __syncthreads();
#pragma unroll
    for (int s = 128; s > 0; s >>= 1) {
        if (tid < s) red[tid] = fmaxf(red[tid], red[tid + s]);
        __syncthreads();
    }
    float m = red[0];
    __syncthreads();

    float e[8];
    e[0] = expf(v0.x - m); e[1] = expf(v0.y - m);
    e[2] = expf(v0.z - m); e[3] = expf(v0.w - m);
    e[4] = expf(v1.x - m); e[5] = expf(v1.y - m);
    e[6] = expf(v1.z - m); e[7] = expf(v1.w - m);

    float ls = (e[0] + e[1]) + (e[2] + e[3]) + (e[4] + e[5]) + (e[6] + e[7]);
    red[tid] = ls; __syncthreads();
#pragma unroll
    for (int s = 128; s > 0; s >>= 1) {
        if (tid < s) red[tid] += red[tid + s];
        __syncthreads();
    }
    float inv = 1.0f / red[0];

    float4 o0, o1;
    o0.x = e[0] * inv * km[tid * 4 + 0];
    o0.y = e[1] * inv * km[tid * 4 + 1];
    o0.z = e[2] * inv * km[tid * 4 + 2];
    o0.w = e[3] * inv * km[tid * 4 + 3];
    o1.x = e[4] * inv * km[1024 + tid * 4 + 0];
    o1.y = e[5] * inv * km[1024 + tid * 4 + 1];
    o1.z = e[6] * inv * km[1024 + tid * 4 + 2];
    o1.w = e[7] * inv * km[1024 + tid * 4 + 3];
    *(float4*)&S[tid * 4] = o0;
    *(float4*)&S[1024 + tid * 4] = o1;
}

// ============================================================================
// O[bh,d,k] = sum_q vh[d,q] * attn[q,k].   M=64, N=T, K=T per (b,h).
// 64x128 tile, BK=32, 256 threads, 4x8 microtile.
// ============================================================================
__global__ __launch_bounds__(256) void av_k()
{
    __shared__ float As[32][68];    // [q][d] (+pad, 16B-aligned rows)
    __shared__ float Bs[32][128];   // [q][k]
    const int bh = blockIdx.z;
    const int b = bh >> 4, h = bh & 15;
    const int kBase = blockIdx.x * 128;
    const float* vb = g_vp + (size_t)b * EE * TT + (size_t)h * DHD * TT;
    const float* Sb = g_sc + (size_t)bh * TT * TT;
    const int tid = threadIdx.x, ty = tid >> 4, tx = tid & 15;

    float acc[4][8];
#pragma unroll
    for (int i = 0; i < 4; i++)
#pragma unroll
        for (int j = 0; j < 8; j++) acc[i][j] = 0.f;

    for (int q0 = 0; q0 < TT; q0 += 32) {
#pragma unroll
        for (int i = 0; i < 2; i++) {            // V tile 64x32, store transposed
            int e = (tid + i * 256) * 4;
            int d = e >> 5, qq = e & 31;
            float4 v4 = *(const float4*)(vb + (size_t)d * TT + q0 + qq);
            As[qq + 0][d] = v4.x; As[qq + 1][d] = v4.y;
            As[qq + 2][d] = v4.z; As[qq + 3][d] = v4.w;
        }
#pragma unroll
        for (int i = 0; i < 4; i++) {            // attn tile 32x128, natural
            int e = (tid + i * 256) * 4;
            int qq = e >> 7, kk = e & 127;
            *(float4*)&Bs[qq][kk] =
                *(const float4*)(Sb + (size_t)(q0 + qq) * TT + kBase + kk);
        }
        __syncthreads();
#pragma unroll
        for (int qq = 0; qq < 32; qq++) {
            float a[4], bb[8];
            *(float4*)&a[0]  = *(const float4*)&As[qq][ty * 4];
            *(float4*)&bb[0] = *(const float4*)&Bs[qq][tx * 8];
            *(float4*)&bb[4] = *(const float4*)&Bs[qq][tx * 8 + 4];
#pragma unroll
            for (int i = 0; i < 4; i++)
#pragma unroll
                for (int j = 0; j < 8; j++)
                    acc[i][j] = fmaf(a[i], bb[j], acc[i][j]);
        }
        __syncthreads();
    }

    float* ob = g_ao + (size_t)b * EE * TT + (size_t)h * DHD * TT;
#pragma unroll
    for (int i = 0; i < 4; i++) {
        int d = ty * 4 + i;
        float4 o0, o1;
        o0.x = acc[i][0]; o0.y = acc[i][1]; o0.z = acc[i][2]; o0.w = acc[i][3];
        o1.x = acc[i][4]; o1.y = acc[i][5]; o1.z = acc[i][6]; o1.w = acc[i][7];
        float* p = ob + (size_t)d * TT + kBase + tx * 8;
        *(float4*)p = o0;
        *(float4*)(p + 4) = o1;
    }
}

// ============================================================================
// launch
// ============================================================================
extern "C" void kernel_launch(void* const* d_in, const int* in_sizes, int n_in,
                              void* d_out, int out_size)
{
    const float* q  = (const float*)d_in[0];
    const float* k  = (const float*)d_in[1];
    const float* v  = (const float*)d_in[2];
    const float* qm = (const float*)d_in[3];
    const float* km = (const float*)d_in[4];
    const float* vm = (const float*)d_in[5];
    const float* Wq = (const float*)d_in[6];
    const float* bq = (const float*)d_in[7];
    const float* Wk = (const float*)d_in[8];
    const float* bk = (const float*)d_in[9];
    const float* Wv = (const float*)d_in[10];
    const float* bv = (const float*)d_in[11];
    const float* Wo = (const float*)d_in[12];
    const float* bo = (const float*)d_in[13];
    float* out = (float*)d_out;

    float *p_qp, *p_kp, *p_vp, *p_ao;
    cudaGetSymbolAddress((void**)&p_qp, g_qp);
    cudaGetSymbolAddress((void**)&p_kp, g_kp);
    cudaGetSymbolAddress((void**)&p_vp, g_vp);
    cudaGetSymbolAddress((void**)&p_ao, g_ao);

    dim3 cgrid(NTOK / 128, EE / 128);
    conv1x1_k<<<cgrid, 256>>>(Wq, q, bq, qm, p_qp);
    conv1x1_k<<<cgrid, 256>>>(Wk, k, bk, km, p_kp);
    conv1x1_k<<<cgrid, 256>>>(Wv, v, bv, vm, p_vp);

    dim3 sgrid(TT / 128, TT / 128, BB * HH);
    scores_k<<<sgrid, 256>>>(qm, km);

    softmax_k<<<BB * HH * TT, 256>>>(km);

    dim3 agrid(TT / 128, 1, BB * HH);
    av_k<<<agrid, 256>>>();

    conv1x1_k<<<cgrid, 256>>>(Wo, p_ao, bo, km, out);
}